// round 14
// baseline (speedup 1.0000x reference)
#include <cuda_runtime.h>
#include <cuda_fp16.h>
#include <cstdint>

// ---------------- problem constants ----------------
#define H_IN   132
#define W_IN   132
#define C_IN   256
#define N_B    2
#define NP     16384
#define KKN    9
#define GRP    4
#define CG     64
#define KDIM   2304
#define M_OFF  72
#define M_PAD  80
#define M_OUT  256
#define BK     32
#define NT     (KDIM / BK)       // 72 k-tiles

typedef unsigned long long ULL;

// ---------------- scratch (device globals) ----------------
__device__ __half g_S[(size_t)N_B * KDIM * NP];         // sampled matrix, fp16, K-major
__device__ __half g_A[(size_t)M_OUT * KDIM];            // deform weights fp16
__device__ __half g_A1[(size_t)M_PAD * KDIM];           // offset weights fp16
#define XPLANE ((size_t)N_B * C_IN * H_IN * 128)
__device__ __half g_X[3 * XPLANE];                      // x fp16, 3 kx-shifted copies
__device__ float g_off[(size_t)N_B * M_OFF * NP];

// ---------------- helpers ----------------
__device__ __forceinline__ uint32_t smem_u32(const void* p) {
    uint32_t a;
    asm("{ .reg .u64 t; cvta.to.shared.u64 t, %1; cvt.u32.u64 %0, t; }" : "=r"(a) : "l"(p));
    return a;
}
__device__ __forceinline__ void cp16(uint32_t dst, const void* src) {
    ULL g;
    asm("cvta.to.global.u64 %0, %1;" : "=l"(g) : "l"(src));
    asm volatile("cp.async.cg.shared.global [%0], [%1], 16;" :: "r"(dst), "l"(g) : "memory");
}
#define CP_COMMIT() asm volatile("cp.async.commit_group;" ::: "memory")
#define CP_WAIT(n)  asm volatile("cp.async.wait_group %0;" :: "n"(n) : "memory")

__device__ __forceinline__ void ldsm_x4(uint32_t* r, uint32_t addr) {
    asm volatile("ldmatrix.sync.aligned.m8n8.x4.shared.b16 {%0,%1,%2,%3}, [%4];"
                 : "=r"(r[0]), "=r"(r[1]), "=r"(r[2]), "=r"(r[3]) : "r"(addr));
}
__device__ __forceinline__ void ldsm_x4t(uint32_t* r, uint32_t addr) {
    asm volatile("ldmatrix.sync.aligned.m8n8.x4.trans.shared.b16 {%0,%1,%2,%3}, [%4];"
                 : "=r"(r[0]), "=r"(r[1]), "=r"(r[2]), "=r"(r[3]) : "r"(addr));
}
__device__ __forceinline__ void mma_f16(float* c, const uint32_t* a, const uint32_t* b) {
    asm volatile(
        "mma.sync.aligned.m16n8k16.row.col.f32.f16.f16.f32 "
        "{%0,%1,%2,%3}, {%4,%5,%6,%7}, {%8,%9}, {%0,%1,%2,%3};"
        : "+f"(c[0]), "+f"(c[1]), "+f"(c[2]), "+f"(c[3])
        : "r"(a[0]), "r"(a[1]), "r"(a[2]), "r"(a[3]), "r"(b[0]), "r"(b[1]));
}

// ================= prep kernels =================
__global__ void prep_w(const float* __restrict__ dw) {
    int idx = blockIdx.x * 256 + threadIdx.x;
    if (idx >= M_OUT * KDIM) return;
    int m = idx / KDIM, j = idx - m * KDIM;
    int g = j / (KKN * CG);
    int r = j - g * (KKN * CG);
    int k = r / CG;
    int c = r - k * CG;
    g_A[idx] = __float2half_rn(dw[((size_t)m * C_IN + g * CG + c) * KKN + k]);
}
__global__ void prep_w1(const float* __restrict__ offw) {
    int idx = blockIdx.x * 256 + threadIdx.x;
    if (idx >= M_PAD * KDIM) return;
    int m = idx / KDIM, j = idx - m * KDIM;
    float v = (m < M_OFF) ? offw[(size_t)m * KDIM + j] : 0.f;
    g_A1[idx] = __float2half_rn(v);
}
__global__ void prep_x(const float* __restrict__ x) {
    size_t idx = (size_t)blockIdx.x * 256 + threadIdx.x;
    if (idx >= XPLANE) return;
    int wo = (int)(idx & 127);
    size_t rest = idx >> 7;
    int y = (int)(rest % H_IN);
    size_t nc = rest / H_IN;
    const float* row = x + (nc * H_IN + y) * W_IN;
    #pragma unroll
    for (int kx = 0; kx < 3; ++kx)
        g_X[kx * XPLANE + idx] = __float2half_rn(row[wo + 2 * kx]);
}

// ================= GEMM1: offsets via HMMA fp16 (80m x 128n x 32k, frag-pipelined) =================
#define A1_PITCH 80
#define B1_PITCH 272
#define SA1 (M_PAD * A1_PITCH)           // 6400
#define SB1 (BK * B1_PITCH)              // 8704
#define OFF_A1 0
#define OFF_B1 SA1
#define BUF1 (SA1 + SB1)                 // 15104
#define SMEM1 (2 * BUF1)                 // 30208

__global__ void __launch_bounds__(256, 2)
gemm1_mma(const float* __restrict__ bias)
{
    extern __shared__ char smem[];
    const uint32_t sb = smem_u32(smem);

    const int tid = threadIdx.x;
    const int l   = tid & 31;
    const int wid = tid >> 5;
    const int n   = blockIdx.z;
    const int p0  = blockIdx.x * 128;
    const int ho0 = blockIdx.x;
    const int wn  = wid * 16;

    const int a_row = ((l >> 3) & 1) * 8 + (l & 7);
    const int a_kb  = (l >> 4) * 8;
    const int b_kr  = ((l >> 3) & 1) * 8 + (l & 7);
    const int b_nb  = (l >> 4) * 8;

    float acc[5][2][4];
    #pragma unroll
    for (int i = 0; i < 5; ++i)
        #pragma unroll
        for (int j = 0; j < 2; ++j)
            #pragma unroll
            for (int q = 0; q < 4; ++q) acc[i][j][q] = 0.f;

    auto load_tile = [&](int kt, int b) {
        uint32_t base = sb + b * BUF1;
        #pragma unroll
        for (int i = 0; i < 2; ++i) {
            int c = tid + i * 256;
            if (c < 320) {
                int r = c >> 2, j = c & 3;
                cp16(base + OFF_A1 + r * A1_PITCH + j * 16,
                     g_A1 + (size_t)r * KDIM + kt + j * 8);
            }
        }
        #pragma unroll
        for (int i = 0; i < 2; ++i) {
            int c  = tid + i * 256;
            int r  = c >> 4;
            int ch = c & 15;
            int j  = kt + r;
            int ci = j / 9;
            int kk = j - ci * 9;
            int ky = kk / 3;
            int kx = kk - ky * 3;
            int y  = ho0 + 2 * ky;
            size_t src = (size_t)kx * XPLANE
                       + (((size_t)n * C_IN + ci) * H_IN + y) * 128 + ch * 8;
            cp16(base + OFF_B1 + r * B1_PITCH + ch * 16, g_X + src);
        }
        CP_COMMIT();
    };

    load_tile(0, 0);

    for (int t = 0; t < NT; ++t) {
        int b = t & 1;
        if (t + 1 < NT) {
            load_tile((t + 1) * BK, b ^ 1);
            CP_WAIT(1);
        } else {
            CP_WAIT(0);
        }
        __syncthreads();

        uint32_t base = sb + b * BUF1;
        // load ALL fragments for both k16 chunks, then run all MMAs
        uint32_t af[2][5][4], bf[2][2][2];
        #pragma unroll
        for (int j = 0; j < 2; ++j) {
            #pragma unroll
            for (int mt = 0; mt < 5; ++mt)
                ldsm_x4(af[j][mt], base + OFF_A1 + (mt * 16 + a_row) * A1_PITCH
                                   + (j * 16 + a_kb) * 2);
            uint32_t r[4];
            ldsm_x4t(r, base + OFF_B1 + (j * 16 + b_kr) * B1_PITCH
                        + (wn + b_nb) * 2);
            bf[j][0][0] = r[0]; bf[j][0][1] = r[1];
            bf[j][1][0] = r[2]; bf[j][1][1] = r[3];
        }
        #pragma unroll
        for (int j = 0; j < 2; ++j)
            #pragma unroll
            for (int mt = 0; mt < 5; ++mt)
                #pragma unroll
                for (int nt = 0; nt < 2; ++nt)
                    mma_f16(acc[mt][nt], af[j][mt], bf[j][nt]);
        __syncthreads();
    }

    float* ob = g_off + (size_t)n * M_OFF * NP + p0 + wn;
    #pragma unroll
    for (int mt = 0; mt < 5; ++mt) {
        int row = mt * 16 + (l >> 2);
        float bv0 = bias[row];
        #pragma unroll
        for (int nt = 0; nt < 2; ++nt) {
            int col = nt * 8 + (l & 3) * 2;
            float* p = ob + (size_t)row * NP + col;
            *reinterpret_cast<float2*>(p) =
                make_float2(acc[mt][nt][0] + bv0, acc[mt][nt][1] + bv0);
        }
        if (mt < 4) {
            float bv1 = bias[row + 8];
            #pragma unroll
            for (int nt = 0; nt < 2; ++nt) {
                int col = nt * 8 + (l & 3) * 2;
                float* p = ob + (size_t)(row + 8) * NP + col;
                *reinterpret_cast<float2*>(p) =
                    make_float2(acc[mt][nt][2] + bv1, acc[mt][nt][3] + bv1);
            }
        }
    }
}

// ================= gather: bilinear sample, 2 px/thread, single fp16 plane =================
__global__ void gather_sampled(const float* __restrict__ x) {
    int n  = blockIdx.z;
    int gk = blockIdx.y;
    int g  = gk / KKN, k = gk % KKN;
    int p  = (blockIdx.x * blockDim.x + threadIdx.x) * 2;
    int ho = p >> 7;
    int ky = k / 3, kx = k % 3;

    const float* offbase = g_off + ((size_t)n * M_OFF + g * 18 + k * 2) * NP + p;
    float2 dy = *reinterpret_cast<const float2*>(offbase);
    float2 dx = *reinterpret_cast<const float2*>(offbase + NP);

    float w00[2], w01[2], w10[2], w11[2];
    int i00[2], i01[2], i10[2], i11[2];
    #pragma unroll
    for (int s = 0; s < 2; ++s) {
        int wo = (p + s) & 127;
        float yf = (s ? dy.y : dy.x) + (float)(ky * 2 + ho);
        float xf = (s ? dx.y : dx.x) + (float)(kx * 2 + wo);
        float y0f = floorf(yf), x0f = floorf(xf);
        float ly = yf - y0f, lx = xf - x0f;
        int y0 = (int)y0f, x0 = (int)x0f;
        int y1 = y0 + 1,  x1 = x0 + 1;

        float a = (1.f - ly) * (1.f - lx);
        float b = (1.f - ly) * lx;
        float c = ly * (1.f - lx);
        float d = ly * lx;

        bool vy0 = (y0 >= 0) & (y0 < H_IN);
        bool vy1 = (y1 >= 0) & (y1 < H_IN);
        bool vx0 = (x0 >= 0) & (x0 < W_IN);
        bool vx1 = (x1 >= 0) & (x1 < W_IN);
        w00[s] = a * (float)(vy0 & vx0);
        w01[s] = b * (float)(vy0 & vx1);
        w10[s] = c * (float)(vy1 & vx0);
        w11[s] = d * (float)(vy1 & vx1);

        int cy0 = min(max(y0, 0), H_IN - 1);
        int cy1 = min(max(y1, 0), H_IN - 1);
        int cx0 = min(max(x0, 0), W_IN - 1);
        int cx1 = min(max(x1, 0), W_IN - 1);
        i00[s] = cy0 * W_IN + cx0;
        i01[s] = cy0 * W_IN + cx1;
        i10[s] = cy1 * W_IN + cx0;
        i11[s] = cy1 * W_IN + cx1;
    }

    const float* xb = x + ((size_t)n * C_IN + g * CG) * (H_IN * W_IN);
    size_t base = ((size_t)n * KDIM + (size_t)(g * KKN + k) * CG) * NP + p;
    __half* sp = g_S + base;

    #pragma unroll 2
    for (int c = 0; c < CG; ++c) {
        const float* xc = xb + c * (H_IN * W_IN);
        float v0 = w00[0] * __ldg(xc + i00[0]) + w01[0] * __ldg(xc + i01[0])
                 + w10[0] * __ldg(xc + i10[0]) + w11[0] * __ldg(xc + i11[0]);
        float v1 = w00[1] * __ldg(xc + i00[1]) + w01[1] * __ldg(xc + i01[1])
                 + w10[1] * __ldg(xc + i10[1]) + w11[1] * __ldg(xc + i11[1]);
        __half2 hp = __floats2half2_rn(v0, v1);
        *reinterpret_cast<uint32_t*>(sp + (size_t)c * NP) = *reinterpret_cast<uint32_t*>(&hp);
    }
}

// ================= GEMM2: HMMA fp16 single-pass, frag-pipelined =================
#define A_PITCH 80
#define B_PITCH 272
#define SA_PLANE (128 * A_PITCH)                 // 10240
#define SB_PLANE (32 * B_PITCH)                  // 8704
#define OFF_A 0
#define OFF_B SA_PLANE
#define BUF_BYTES (SA_PLANE + SB_PLANE)          // 18944
#define SMEM2_BYTES (2 * BUF_BYTES)              // 37888

__global__ void __launch_bounds__(256, 2)
gemm2_mma(float* __restrict__ out)
{
    extern __shared__ char smem[];
    const uint32_t sb = smem_u32(smem);

    const int tid = threadIdx.x;
    const int wid = tid >> 5;
    const int l   = tid & 31;

    const int my = blockIdx.x;
    const int bx = blockIdx.y;
    const int n  = blockIdx.z;

    const int wm = (wid & 1) * 64;
    const int wn = (wid >> 1) * 32;

    const __half* Ap = g_A + (size_t)my * 128 * KDIM;
    const __half* Sp = g_S + (size_t)n * KDIM * NP + (size_t)bx * 128;

    const int a_row = ((l >> 3) & 1) * 8 + (l & 7);
    const int a_kb  = (l >> 4) * 8;
    const int b_kr  = ((l >> 3) & 1) * 8 + (l & 7);
    const int b_nb  = (l >> 4) * 8;

    float acc[4][4][4];
    #pragma unroll
    for (int i = 0; i < 4; ++i)
        #pragma unroll
        for (int j = 0; j < 4; ++j)
            #pragma unroll
            for (int q = 0; q < 4; ++q) acc[i][j][q] = 0.f;

    auto load_tile = [&](int kt, int b) {
        uint32_t base = sb + b * BUF_BYTES;
        #pragma unroll
        for (int i = 0; i < 2; ++i) {
            int c = tid + i * 256;
            int r = c >> 2, j = c & 3;
            cp16(base + OFF_A + r * A_PITCH + j * 16, Ap + (size_t)r * KDIM + kt + j * 8);
        }
        #pragma unroll
        for (int i = 0; i < 2; ++i) {
            int c = tid + i * 256;
            int r = c >> 4, j = c & 15;
            cp16(base + OFF_B + r * B_PITCH + j * 16, Sp + (size_t)(kt + r) * NP + j * 8);
        }
        CP_COMMIT();
    };

    load_tile(0, 0);

    for (int t = 0; t < NT; ++t) {
        int b = t & 1;
        if (t + 1 < NT) {
            load_tile((t + 1) * BK, b ^ 1);
            CP_WAIT(1);
        } else {
            CP_WAIT(0);
        }
        __syncthreads();

        uint32_t base = sb + b * BUF_BYTES;
        // load ALL fragments for both k16 chunks, then run all MMAs
        uint32_t af[2][4][4], bf[2][4][2];
        #pragma unroll
        for (int j = 0; j < 2; ++j) {
            #pragma unroll
            for (int mt = 0; mt < 4; ++mt)
                ldsm_x4(af[j][mt], base + OFF_A + (wm + mt * 16 + a_row) * A_PITCH
                                   + (j * 16 + a_kb) * 2);
            #pragma unroll
            for (int nt2 = 0; nt2 < 2; ++nt2) {
                uint32_t r[4];
                ldsm_x4t(r, base + OFF_B + (j * 16 + b_kr) * B_PITCH
                            + (wn + nt2 * 16 + b_nb) * 2);
                bf[j][nt2*2][0] = r[0]; bf[j][nt2*2][1] = r[1];
                bf[j][nt2*2+1][0] = r[2]; bf[j][nt2*2+1][1] = r[3];
            }
        }
        #pragma unroll
        for (int j = 0; j < 2; ++j)
            #pragma unroll
            for (int mt = 0; mt < 4; ++mt)
                #pragma unroll
                for (int nt = 0; nt < 4; ++nt)
                    mma_f16(acc[mt][nt], af[j][mt], bf[j][nt]);
        __syncthreads();
    }

    float* ob = out + ((size_t)n * M_OUT + my * 128 + wm) * NP + (size_t)bx * 128 + wn;
    #pragma unroll
    for (int mt = 0; mt < 4; ++mt) {
        #pragma unroll
        for (int nt = 0; nt < 4; ++nt) {
            int row = mt * 16 + (l >> 2);
            int col = nt * 8 + (l & 3) * 2;
            float* p0 = ob + (size_t)row * NP + col;
            *reinterpret_cast<float2*>(p0) =
                make_float2(acc[mt][nt][0], acc[mt][nt][1]);
            *reinterpret_cast<float2*>(p0 + 8 * NP) =
                make_float2(acc[mt][nt][2], acc[mt][nt][3]);
        }
    }
}

// ---------------- launch ----------------
extern "C" void kernel_launch(void* const* d_in, const int* in_sizes, int n_in,
                              void* d_out, int out_size) {
    const float* x    = (const float*)d_in[0];
    const float* offw = (const float*)d_in[1];
    const float* offb = (const float*)d_in[2];
    const float* dw   = (const float*)d_in[3];
    float* out = (float*)d_out;

    cudaFuncSetAttribute(gemm1_mma, cudaFuncAttributeMaxDynamicSharedMemorySize, SMEM1);
    cudaFuncSetAttribute(gemm2_mma, cudaFuncAttributeMaxDynamicSharedMemorySize, SMEM2_BYTES);

    prep_w <<<(M_OUT * KDIM + 255) / 256, 256>>>(dw);
    prep_w1<<<(M_PAD * KDIM + 255) / 256, 256>>>(offw);
    prep_x <<<(int)((XPLANE + 255) / 256), 256>>>(x);
    // 1) offsets via tensor cores (fp16, frag-pipelined)
    {
        dim3 grid(NP / 128, 1, N_B);
        gemm1_mma<<<grid, 256, SMEM1>>>(offb);
    }
    // 2) bilinear sampled matrix -> single fp16 plane
    {
        dim3 grid(NP / 512, GRP * KKN, N_B);
        gather_sampled<<<grid, 256>>>(x);
    }
    // 3) out = dw @ sampled (fp16, frag-pipelined)
    {
        dim3 grid(2, NP / 128, N_B);
        gemm2_mma<<<grid, 256, SMEM2_BYTES>>>(out);
    }
}

// round 15
// speedup vs baseline: 1.0297x; 1.0297x over previous
#include <cuda_runtime.h>
#include <cuda_fp16.h>
#include <cstdint>

// ---------------- problem constants ----------------
#define H_IN   132
#define W_IN   132
#define C_IN   256
#define N_B    2
#define NP     16384
#define KKN    9
#define GRP    4
#define CG     64
#define KDIM   2304
#define M_OFF  72
#define M_PAD  80
#define M_OUT  256
#define BK     32
#define NT     (KDIM / BK)       // 72 k-tiles

typedef unsigned long long ULL;

// ---------------- scratch (device globals) ----------------
__device__ __half g_S[(size_t)N_B * KDIM * NP];         // sampled matrix, fp16, K-major
__device__ __half g_A[(size_t)M_OUT * KDIM];            // deform weights fp16
__device__ __half g_A1[(size_t)M_PAD * KDIM];           // offset weights fp16
#define XPLANE ((size_t)N_B * C_IN * H_IN * 128)
__device__ __half g_X[3 * XPLANE];                      // x fp16, 3 kx-shifted copies (gemm1)
#define XFULL ((size_t)N_B * C_IN * H_IN * W_IN)
__device__ __half g_Xf[XFULL];                          // full fp16 copy of x (gather)
__device__ float g_off[(size_t)N_B * M_OFF * NP];

// ---------------- helpers ----------------
__device__ __forceinline__ uint32_t smem_u32(const void* p) {
    uint32_t a;
    asm("{ .reg .u64 t; cvta.to.shared.u64 t, %1; cvt.u32.u64 %0, t; }" : "=r"(a) : "l"(p));
    return a;
}
__device__ __forceinline__ void cp16(uint32_t dst, const void* src) {
    ULL g;
    asm("cvta.to.global.u64 %0, %1;" : "=l"(g) : "l"(src));
    asm volatile("cp.async.cg.shared.global [%0], [%1], 16;" :: "r"(dst), "l"(g) : "memory");
}
#define CP_COMMIT() asm volatile("cp.async.commit_group;" ::: "memory")
#define CP_WAIT(n)  asm volatile("cp.async.wait_group %0;" :: "n"(n) : "memory")

__device__ __forceinline__ void ldsm_x4(uint32_t* r, uint32_t addr) {
    asm volatile("ldmatrix.sync.aligned.m8n8.x4.shared.b16 {%0,%1,%2,%3}, [%4];"
                 : "=r"(r[0]), "=r"(r[1]), "=r"(r[2]), "=r"(r[3]) : "r"(addr));
}
__device__ __forceinline__ void ldsm_x4t(uint32_t* r, uint32_t addr) {
    asm volatile("ldmatrix.sync.aligned.m8n8.x4.trans.shared.b16 {%0,%1,%2,%3}, [%4];"
                 : "=r"(r[0]), "=r"(r[1]), "=r"(r[2]), "=r"(r[3]) : "r"(addr));
}
__device__ __forceinline__ void mma_f16(float* c, const uint32_t* a, const uint32_t* b) {
    asm volatile(
        "mma.sync.aligned.m16n8k16.row.col.f32.f16.f16.f32 "
        "{%0,%1,%2,%3}, {%4,%5,%6,%7}, {%8,%9}, {%0,%1,%2,%3};"
        : "+f"(c[0]), "+f"(c[1]), "+f"(c[2]), "+f"(c[3])
        : "r"(a[0]), "r"(a[1]), "r"(a[2]), "r"(a[3]), "r"(b[0]), "r"(b[1]));
}

// ================= prep kernels =================
__global__ void prep_w(const float* __restrict__ dw) {
    int idx = blockIdx.x * 256 + threadIdx.x;
    if (idx >= M_OUT * KDIM) return;
    int m = idx / KDIM, j = idx - m * KDIM;
    int g = j / (KKN * CG);
    int r = j - g * (KKN * CG);
    int k = r / CG;
    int c = r - k * CG;
    g_A[idx] = __float2half_rn(dw[((size_t)m * C_IN + g * CG + c) * KKN + k]);
}
__global__ void prep_w1(const float* __restrict__ offw) {
    int idx = blockIdx.x * 256 + threadIdx.x;
    if (idx >= M_PAD * KDIM) return;
    int m = idx / KDIM, j = idx - m * KDIM;
    float v = (m < M_OFF) ? offw[(size_t)m * KDIM + j] : 0.f;
    g_A1[idx] = __float2half_rn(v);
}
__global__ void prep_x(const float* __restrict__ x) {
    size_t idx = (size_t)blockIdx.x * 256 + threadIdx.x;
    if (idx >= XPLANE) return;
    int wo = (int)(idx & 127);
    size_t rest = idx >> 7;
    int y = (int)(rest % H_IN);
    size_t nc = rest / H_IN;
    const float* row = x + (nc * H_IN + y) * W_IN;
    #pragma unroll
    for (int kx = 0; kx < 3; ++kx)
        g_X[kx * XPLANE + idx] = __float2half_rn(row[wo + 2 * kx]);
}
__global__ void prep_xf(const float* __restrict__ x) {
    size_t idx = (size_t)blockIdx.x * 256 + threadIdx.x;
    if (idx >= XFULL) return;
    g_Xf[idx] = __float2half_rn(x[idx]);
}

// ================= GEMM1: offsets via HMMA fp16 single-pass (80m x 128n x 32k) =================
#define A1_PITCH 80
#define B1_PITCH 272
#define SA1 (M_PAD * A1_PITCH)           // 6400
#define SB1 (BK * B1_PITCH)              // 8704
#define OFF_A1 0
#define OFF_B1 SA1
#define BUF1 (SA1 + SB1)                 // 15104
#define SMEM1 (2 * BUF1)                 // 30208

__global__ void __launch_bounds__(256, 2)
gemm1_mma(const float* __restrict__ bias)
{
    extern __shared__ char smem[];
    const uint32_t sb = smem_u32(smem);

    const int tid = threadIdx.x;
    const int l   = tid & 31;
    const int wid = tid >> 5;
    const int n   = blockIdx.z;
    const int p0  = blockIdx.x * 128;
    const int ho0 = blockIdx.x;
    const int wn  = wid * 16;

    const int a_row = ((l >> 3) & 1) * 8 + (l & 7);
    const int a_kb  = (l >> 4) * 8;
    const int b_kr  = ((l >> 3) & 1) * 8 + (l & 7);
    const int b_nb  = (l >> 4) * 8;

    float acc[5][2][4];
    #pragma unroll
    for (int i = 0; i < 5; ++i)
        #pragma unroll
        for (int j = 0; j < 2; ++j)
            #pragma unroll
            for (int q = 0; q < 4; ++q) acc[i][j][q] = 0.f;

    auto load_tile = [&](int kt, int b) {
        uint32_t base = sb + b * BUF1;
        #pragma unroll
        for (int i = 0; i < 2; ++i) {
            int c = tid + i * 256;
            if (c < 320) {
                int r = c >> 2, j = c & 3;
                cp16(base + OFF_A1 + r * A1_PITCH + j * 16,
                     g_A1 + (size_t)r * KDIM + kt + j * 8);
            }
        }
        #pragma unroll
        for (int i = 0; i < 2; ++i) {
            int c  = tid + i * 256;
            int r  = c >> 4;
            int ch = c & 15;
            int j  = kt + r;
            int ci = j / 9;
            int kk = j - ci * 9;
            int ky = kk / 3;
            int kx = kk - ky * 3;
            int y  = ho0 + 2 * ky;
            size_t src = (size_t)kx * XPLANE
                       + (((size_t)n * C_IN + ci) * H_IN + y) * 128 + ch * 8;
            cp16(base + OFF_B1 + r * B1_PITCH + ch * 16, g_X + src);
        }
        CP_COMMIT();
    };

    load_tile(0, 0);

    for (int t = 0; t < NT; ++t) {
        int b = t & 1;
        if (t + 1 < NT) {
            load_tile((t + 1) * BK, b ^ 1);
            CP_WAIT(1);
        } else {
            CP_WAIT(0);
        }
        __syncthreads();

        uint32_t base = sb + b * BUF1;
        #pragma unroll
        for (int k16 = 0; k16 < BK; k16 += 16) {
            uint32_t ah[5][4], bf[2][2];
            #pragma unroll
            for (int mt = 0; mt < 5; ++mt)
                ldsm_x4(ah[mt], base + OFF_A1 + (mt * 16 + a_row) * A1_PITCH
                                + (k16 + a_kb) * 2);
            {
                uint32_t r[4];
                ldsm_x4t(r, base + OFF_B1 + (k16 + b_kr) * B1_PITCH
                            + (wn + b_nb) * 2);
                bf[0][0] = r[0]; bf[0][1] = r[1];
                bf[1][0] = r[2]; bf[1][1] = r[3];
            }
            #pragma unroll
            for (int mt = 0; mt < 5; ++mt)
                #pragma unroll
                for (int nt = 0; nt < 2; ++nt)
                    mma_f16(acc[mt][nt], ah[mt], bf[nt]);
        }
        __syncthreads();
    }

    float* ob = g_off + (size_t)n * M_OFF * NP + p0 + wn;
    #pragma unroll
    for (int mt = 0; mt < 5; ++mt) {
        int row = mt * 16 + (l >> 2);
        float bv0 = bias[row];
        #pragma unroll
        for (int nt = 0; nt < 2; ++nt) {
            int col = nt * 8 + (l & 3) * 2;
            float* p = ob + (size_t)row * NP + col;
            *reinterpret_cast<float2*>(p) =
                make_float2(acc[mt][nt][0] + bv0, acc[mt][nt][1] + bv0);
        }
        if (mt < 4) {
            float bv1 = bias[row + 8];
            #pragma unroll
            for (int nt = 0; nt < 2; ++nt) {
                int col = nt * 8 + (l & 3) * 2;
                float* p = ob + (size_t)(row + 8) * NP + col;
                *reinterpret_cast<float2*>(p) =
                    make_float2(acc[mt][nt][2] + bv1, acc[mt][nt][3] + bv1);
            }
        }
    }
}

// ================= gather: bilinear from fp16 x, 2 px/thread =================
__global__ void gather_sampled() {
    int n  = blockIdx.z;
    int gk = blockIdx.y;
    int g  = gk / KKN, k = gk % KKN;
    int p  = (blockIdx.x * blockDim.x + threadIdx.x) * 2;
    int ho = p >> 7;
    int ky = k / 3, kx = k % 3;

    const float* offbase = g_off + ((size_t)n * M_OFF + g * 18 + k * 2) * NP + p;
    float2 dy = *reinterpret_cast<const float2*>(offbase);
    float2 dx = *reinterpret_cast<const float2*>(offbase + NP);

    float w00[2], w01[2], w10[2], w11[2];
    int i00[2], i01[2], i10[2], i11[2];
    #pragma unroll
    for (int s = 0; s < 2; ++s) {
        int wo = (p + s) & 127;
        float yf = (s ? dy.y : dy.x) + (float)(ky * 2 + ho);
        float xf = (s ? dx.y : dx.x) + (float)(kx * 2 + wo);
        float y0f = floorf(yf), x0f = floorf(xf);
        float ly = yf - y0f, lx = xf - x0f;
        int y0 = (int)y0f, x0 = (int)x0f;
        int y1 = y0 + 1,  x1 = x0 + 1;

        float a = (1.f - ly) * (1.f - lx);
        float b = (1.f - ly) * lx;
        float c = ly * (1.f - lx);
        float d = ly * lx;

        bool vy0 = (y0 >= 0) & (y0 < H_IN);
        bool vy1 = (y1 >= 0) & (y1 < H_IN);
        bool vx0 = (x0 >= 0) & (x0 < W_IN);
        bool vx1 = (x1 >= 0) & (x1 < W_IN);
        w00[s] = a * (float)(vy0 & vx0);
        w01[s] = b * (float)(vy0 & vx1);
        w10[s] = c * (float)(vy1 & vx0);
        w11[s] = d * (float)(vy1 & vx1);

        int cy0 = min(max(y0, 0), H_IN - 1);
        int cy1 = min(max(y1, 0), H_IN - 1);
        int cx0 = min(max(x0, 0), W_IN - 1);
        int cx1 = min(max(x1, 0), W_IN - 1);
        i00[s] = cy0 * W_IN + cx0;
        i01[s] = cy0 * W_IN + cx1;
        i10[s] = cy1 * W_IN + cx0;
        i11[s] = cy1 * W_IN + cx1;
    }

    const __half* xb = g_Xf + ((size_t)n * C_IN + g * CG) * (H_IN * W_IN);
    size_t base = ((size_t)n * KDIM + (size_t)(g * KKN + k) * CG) * NP + p;
    __half* sp = g_S + base;

    #pragma unroll 2
    for (int c = 0; c < CG; ++c) {
        const __half* xc = xb + (size_t)c * (H_IN * W_IN);
        float v0 = w00[0] * __half2float(__ldg(xc + i00[0]))
                 + w01[0] * __half2float(__ldg(xc + i01[0]))
                 + w10[0] * __half2float(__ldg(xc + i10[0]))
                 + w11[0] * __half2float(__ldg(xc + i11[0]));
        float v1 = w00[1] * __half2float(__ldg(xc + i00[1]))
                 + w01[1] * __half2float(__ldg(xc + i01[1]))
                 + w10[1] * __half2float(__ldg(xc + i10[1]))
                 + w11[1] * __half2float(__ldg(xc + i11[1]));
        __half2 hp = __floats2half2_rn(v0, v1);
        *reinterpret_cast<uint32_t*>(sp + (size_t)c * NP) = *reinterpret_cast<uint32_t*>(&hp);
    }
}

// ================= GEMM2: HMMA fp16 single-pass (round-13 best) =================
#define A_PITCH 80
#define B_PITCH 272
#define SA_PLANE (128 * A_PITCH)                 // 10240
#define SB_PLANE (32 * B_PITCH)                  // 8704
#define OFF_A 0
#define OFF_B SA_PLANE
#define BUF_BYTES (SA_PLANE + SB_PLANE)          // 18944
#define SMEM2_BYTES (2 * BUF_BYTES)              // 37888

__global__ void __launch_bounds__(256, 2)
gemm2_mma(float* __restrict__ out)
{
    extern __shared__ char smem[];
    const uint32_t sb = smem_u32(smem);

    const int tid = threadIdx.x;
    const int wid = tid >> 5;
    const int l   = tid & 31;

    const int my = blockIdx.x;
    const int bx = blockIdx.y;
    const int n  = blockIdx.z;

    const int wm = (wid & 1) * 64;
    const int wn = (wid >> 1) * 32;

    const __half* Ap = g_A + (size_t)my * 128 * KDIM;
    const __half* Sp = g_S + (size_t)n * KDIM * NP + (size_t)bx * 128;

    const int a_row = ((l >> 3) & 1) * 8 + (l & 7);
    const int a_kb  = (l >> 4) * 8;
    const int b_kr  = ((l >> 3) & 1) * 8 + (l & 7);
    const int b_nb  = (l >> 4) * 8;

    float acc[4][4][4];
    #pragma unroll
    for (int i = 0; i < 4; ++i)
        #pragma unroll
        for (int j = 0; j < 4; ++j)
            #pragma unroll
            for (int q = 0; q < 4; ++q) acc[i][j][q] = 0.f;

    auto load_tile = [&](int kt, int b) {
        uint32_t base = sb + b * BUF_BYTES;
        #pragma unroll
        for (int i = 0; i < 2; ++i) {
            int c = tid + i * 256;
            int r = c >> 2, j = c & 3;
            cp16(base + OFF_A + r * A_PITCH + j * 16, Ap + (size_t)r * KDIM + kt + j * 8);
        }
        #pragma unroll
        for (int i = 0; i < 2; ++i) {
            int c = tid + i * 256;
            int r = c >> 4, j = c & 15;
            cp16(base + OFF_B + r * B_PITCH + j * 16, Sp + (size_t)(kt + r) * NP + j * 8);
        }
        CP_COMMIT();
    };

    load_tile(0, 0);

    for (int t = 0; t < NT; ++t) {
        int b = t & 1;
        if (t + 1 < NT) {
            load_tile((t + 1) * BK, b ^ 1);
            CP_WAIT(1);
        } else {
            CP_WAIT(0);
        }
        __syncthreads();

        uint32_t base = sb + b * BUF_BYTES;
        #pragma unroll
        for (int k16 = 0; k16 < BK; k16 += 16) {
            uint32_t af[4][4], bf[4][2];
            #pragma unroll
            for (int mt = 0; mt < 4; ++mt)
                ldsm_x4(af[mt], base + OFF_A + (wm + mt * 16 + a_row) * A_PITCH
                                + (k16 + a_kb) * 2);
            #pragma unroll
            for (int nt2 = 0; nt2 < 2; ++nt2) {
                uint32_t r[4];
                ldsm_x4t(r, base + OFF_B + (k16 + b_kr) * B_PITCH
                            + (wn + nt2 * 16 + b_nb) * 2);
                bf[nt2*2][0] = r[0]; bf[nt2*2][1] = r[1];
                bf[nt2*2+1][0] = r[2]; bf[nt2*2+1][1] = r[3];
            }
            #pragma unroll
            for (int mt = 0; mt < 4; ++mt)
                #pragma unroll
                for (int nt = 0; nt < 4; ++nt)
                    mma_f16(acc[mt][nt], af[mt], bf[nt]);
        }
        __syncthreads();
    }

    float* ob = out + ((size_t)n * M_OUT + my * 128 + wm) * NP + (size_t)bx * 128 + wn;
    #pragma unroll
    for (int mt = 0; mt < 4; ++mt) {
        #pragma unroll
        for (int nt = 0; nt < 4; ++nt) {
            int row = mt * 16 + (l >> 2);
            int col = nt * 8 + (l & 3) * 2;
            float* p0 = ob + (size_t)row * NP + col;
            *reinterpret_cast<float2*>(p0) =
                make_float2(acc[mt][nt][0], acc[mt][nt][1]);
            *reinterpret_cast<float2*>(p0 + 8 * NP) =
                make_float2(acc[mt][nt][2], acc[mt][nt][3]);
        }
    }
}

// ---------------- launch ----------------
extern "C" void kernel_launch(void* const* d_in, const int* in_sizes, int n_in,
                              void* d_out, int out_size) {
    const float* x    = (const float*)d_in[0];
    const float* offw = (const float*)d_in[1];
    const float* offb = (const float*)d_in[2];
    const float* dw   = (const float*)d_in[3];
    float* out = (float*)d_out;

    cudaFuncSetAttribute(gemm1_mma, cudaFuncAttributeMaxDynamicSharedMemorySize, SMEM1);
    cudaFuncSetAttribute(gemm2_mma, cudaFuncAttributeMaxDynamicSharedMemorySize, SMEM2_BYTES);

    prep_w <<<(M_OUT * KDIM + 255) / 256, 256>>>(dw);
    prep_w1<<<(M_PAD * KDIM + 255) / 256, 256>>>(offw);
    prep_x <<<(int)((XPLANE + 255) / 256), 256>>>(x);
    prep_xf<<<(int)((XFULL + 255) / 256), 256>>>(x);
    // 1) offsets via tensor cores (fp16 single-pass)
    {
        dim3 grid(NP / 128, 1, N_B);
        gemm1_mma<<<grid, 256, SMEM1>>>(offb);
    }
    // 2) bilinear sampled matrix from fp16 x -> single fp16 plane
    {
        dim3 grid(NP / 512, GRP * KKN, N_B);
        gather_sampled<<<grid, 256>>>();
    }
    // 3) out = dw @ sampled (fp16 single-pass)
    {
        dim3 grid(2, NP / 128, N_B);
        gemm2_mma<<<grid, 256, SMEM2_BYTES>>>(out);
    }
}

// round 16
// speedup vs baseline: 1.1089x; 1.0769x over previous
#include <cuda_runtime.h>
#include <cuda_fp16.h>
#include <cstdint>

// ---------------- problem constants ----------------
#define H_IN   132
#define W_IN   132
#define C_IN   256
#define N_B    2
#define NP     16384
#define KKN    9
#define GRP    4
#define CG     64
#define KDIM   2304
#define M_OFF  72
#define M_PAD  80
#define M_OUT  256
#define BK     32
#define NT     (KDIM / BK)       // 72 k-tiles

typedef unsigned long long ULL;

// ---------------- scratch (device globals) ----------------
__device__ __half g_S[(size_t)N_B * KDIM * NP];         // sampled matrix, fp16, K-major
__device__ __half g_A[(size_t)M_OUT * KDIM];            // deform weights fp16
__device__ __half g_A1[(size_t)M_PAD * KDIM];           // offset weights fp16
#define XPLANE ((size_t)N_B * C_IN * H_IN * 128)
__device__ __half g_X[3 * XPLANE];                      // x fp16, 3 kx-shifted copies (gemm1)
#define XFULL ((size_t)N_B * C_IN * H_IN * W_IN)
__device__ __half g_Xf[XFULL];                          // full fp16 copy of x (gather)
__device__ float g_off[(size_t)N_B * M_OFF * NP];

// ---------------- helpers ----------------
__device__ __forceinline__ uint32_t smem_u32(const void* p) {
    uint32_t a;
    asm("{ .reg .u64 t; cvta.to.shared.u64 t, %1; cvt.u32.u64 %0, t; }" : "=r"(a) : "l"(p));
    return a;
}
__device__ __forceinline__ void cp16(uint32_t dst, const void* src) {
    ULL g;
    asm("cvta.to.global.u64 %0, %1;" : "=l"(g) : "l"(src));
    asm volatile("cp.async.cg.shared.global [%0], [%1], 16;" :: "r"(dst), "l"(g) : "memory");
}
#define CP_COMMIT() asm volatile("cp.async.commit_group;" ::: "memory")
#define CP_WAIT(n)  asm volatile("cp.async.wait_group %0;" :: "n"(n) : "memory")

__device__ __forceinline__ void ldsm_x4(uint32_t* r, uint32_t addr) {
    asm volatile("ldmatrix.sync.aligned.m8n8.x4.shared.b16 {%0,%1,%2,%3}, [%4];"
                 : "=r"(r[0]), "=r"(r[1]), "=r"(r[2]), "=r"(r[3]) : "r"(addr));
}
__device__ __forceinline__ void ldsm_x4t(uint32_t* r, uint32_t addr) {
    asm volatile("ldmatrix.sync.aligned.m8n8.x4.trans.shared.b16 {%0,%1,%2,%3}, [%4];"
                 : "=r"(r[0]), "=r"(r[1]), "=r"(r[2]), "=r"(r[3]) : "r"(addr));
}
__device__ __forceinline__ void mma_f16(float* c, const uint32_t* a, const uint32_t* b) {
    asm volatile(
        "mma.sync.aligned.m16n8k16.row.col.f32.f16.f16.f32 "
        "{%0,%1,%2,%3}, {%4,%5,%6,%7}, {%8,%9}, {%0,%1,%2,%3};"
        : "+f"(c[0]), "+f"(c[1]), "+f"(c[2]), "+f"(c[3])
        : "r"(a[0]), "r"(a[1]), "r"(a[2]), "r"(a[3]), "r"(b[0]), "r"(b[1]));
}

// ================= prep kernels =================
__global__ void prep_w(const float* __restrict__ dw) {
    int idx = blockIdx.x * 256 + threadIdx.x;
    if (idx >= M_OUT * KDIM) return;
    int m = idx / KDIM, j = idx - m * KDIM;
    int g = j / (KKN * CG);
    int r = j - g * (KKN * CG);
    int k = r / CG;
    int c = r - k * CG;
    g_A[idx] = __float2half_rn(dw[((size_t)m * C_IN + g * CG + c) * KKN + k]);
}
__global__ void prep_w1(const float* __restrict__ offw) {
    int idx = blockIdx.x * 256 + threadIdx.x;
    if (idx >= M_PAD * KDIM) return;
    int m = idx / KDIM, j = idx - m * KDIM;
    float v = (m < M_OFF) ? offw[(size_t)m * KDIM + j] : 0.f;
    g_A1[idx] = __float2half_rn(v);
}
// fused: read x once, write full fp16 copy + 3 kx-shifted 128-wide planes
__global__ void prep_xall(const float* __restrict__ x) {
    size_t idx = (size_t)blockIdx.x * 256 + threadIdx.x;
    if (idx >= XFULL) return;
    __half h = __float2half_rn(x[idx]);
    g_Xf[idx] = h;
    int wo = (int)(idx % W_IN);
    size_t rest = idx / W_IN;            // (n*C + ci)*H + y
    #pragma unroll
    for (int kx = 0; kx < 3; ++kx) {
        int w0 = wo - 2 * kx;
        if (w0 >= 0 && w0 < 128)
            g_X[kx * XPLANE + rest * 128 + w0] = h;
    }
}

// ================= GEMM1: offsets via HMMA fp16 single-pass (80m x 128n x 32k) =================
#define A1_PITCH 80
#define B1_PITCH 272
#define SA1 (M_PAD * A1_PITCH)           // 6400
#define SB1 (BK * B1_PITCH)              // 8704
#define OFF_A1 0
#define OFF_B1 SA1
#define BUF1 (SA1 + SB1)                 // 15104
#define SMEM1 (2 * BUF1)                 // 30208

__global__ void __launch_bounds__(256, 2)
gemm1_mma(const float* __restrict__ bias)
{
    extern __shared__ char smem[];
    const uint32_t sb = smem_u32(smem);

    const int tid = threadIdx.x;
    const int l   = tid & 31;
    const int wid = tid >> 5;
    const int n   = blockIdx.z;
    const int p0  = blockIdx.x * 128;
    const int ho0 = blockIdx.x;
    const int wn  = wid * 16;

    const int a_row = ((l >> 3) & 1) * 8 + (l & 7);
    const int a_kb  = (l >> 4) * 8;
    const int b_kr  = ((l >> 3) & 1) * 8 + (l & 7);
    const int b_nb  = (l >> 4) * 8;

    float acc[5][2][4];
    #pragma unroll
    for (int i = 0; i < 5; ++i)
        #pragma unroll
        for (int j = 0; j < 2; ++j)
            #pragma unroll
            for (int q = 0; q < 4; ++q) acc[i][j][q] = 0.f;

    auto load_tile = [&](int kt, int b) {
        uint32_t base = sb + b * BUF1;
        #pragma unroll
        for (int i = 0; i < 2; ++i) {
            int c = tid + i * 256;
            if (c < 320) {
                int r = c >> 2, j = c & 3;
                cp16(base + OFF_A1 + r * A1_PITCH + j * 16,
                     g_A1 + (size_t)r * KDIM + kt + j * 8);
            }
        }
        #pragma unroll
        for (int i = 0; i < 2; ++i) {
            int c  = tid + i * 256;
            int r  = c >> 4;
            int ch = c & 15;
            int j  = kt + r;
            int ci = j / 9;
            int kk = j - ci * 9;
            int ky = kk / 3;
            int kx = kk - ky * 3;
            int y  = ho0 + 2 * ky;
            size_t src = (size_t)kx * XPLANE
                       + (((size_t)n * C_IN + ci) * H_IN + y) * 128 + ch * 8;
            cp16(base + OFF_B1 + r * B1_PITCH + ch * 16, g_X + src);
        }
        CP_COMMIT();
    };

    load_tile(0, 0);

    for (int t = 0; t < NT; ++t) {
        int b = t & 1;
        if (t + 1 < NT) {
            load_tile((t + 1) * BK, b ^ 1);
            CP_WAIT(1);
        } else {
            CP_WAIT(0);
        }
        __syncthreads();

        uint32_t base = sb + b * BUF1;
        #pragma unroll
        for (int k16 = 0; k16 < BK; k16 += 16) {
            uint32_t ah[5][4], bf[2][2];
            #pragma unroll
            for (int mt = 0; mt < 5; ++mt)
                ldsm_x4(ah[mt], base + OFF_A1 + (mt * 16 + a_row) * A1_PITCH
                                + (k16 + a_kb) * 2);
            {
                uint32_t r[4];
                ldsm_x4t(r, base + OFF_B1 + (k16 + b_kr) * B1_PITCH
                            + (wn + b_nb) * 2);
                bf[0][0] = r[0]; bf[0][1] = r[1];
                bf[1][0] = r[2]; bf[1][1] = r[3];
            }
            #pragma unroll
            for (int mt = 0; mt < 5; ++mt)
                #pragma unroll
                for (int nt = 0; nt < 2; ++nt)
                    mma_f16(acc[mt][nt], ah[mt], bf[nt]);
        }
        __syncthreads();
    }

    float* ob = g_off + (size_t)n * M_OFF * NP + p0 + wn;
    #pragma unroll
    for (int mt = 0; mt < 5; ++mt) {
        int row = mt * 16 + (l >> 2);
        float bv0 = bias[row];
        #pragma unroll
        for (int nt = 0; nt < 2; ++nt) {
            int col = nt * 8 + (l & 3) * 2;
            float* p = ob + (size_t)row * NP + col;
            *reinterpret_cast<float2*>(p) =
                make_float2(acc[mt][nt][0] + bv0, acc[mt][nt][1] + bv0);
        }
        if (mt < 4) {
            float bv1 = bias[row + 8];
            #pragma unroll
            for (int nt = 0; nt < 2; ++nt) {
                int col = nt * 8 + (l & 3) * 2;
                float* p = ob + (size_t)(row + 8) * NP + col;
                *reinterpret_cast<float2*>(p) =
                    make_float2(acc[mt][nt][2] + bv1, acc[mt][nt][3] + bv1);
            }
        }
    }
}

// ================= gather: bilinear from fp16 x, 2 px/thread =================
__global__ void gather_sampled() {
    int n  = blockIdx.z;
    int gk = blockIdx.y;
    int g  = gk / KKN, k = gk % KKN;
    int p  = (blockIdx.x * blockDim.x + threadIdx.x) * 2;
    int ho = p >> 7;
    int ky = k / 3, kx = k % 3;

    const float* offbase = g_off + ((size_t)n * M_OFF + g * 18 + k * 2) * NP + p;
    float2 dy = *reinterpret_cast<const float2*>(offbase);
    float2 dx = *reinterpret_cast<const float2*>(offbase + NP);

    float w00[2], w01[2], w10[2], w11[2];
    int i00[2], i01[2], i10[2], i11[2];
    #pragma unroll
    for (int s = 0; s < 2; ++s) {
        int wo = (p + s) & 127;
        float yf = (s ? dy.y : dy.x) + (float)(ky * 2 + ho);
        float xf = (s ? dx.y : dx.x) + (float)(kx * 2 + wo);
        float y0f = floorf(yf), x0f = floorf(xf);
        float ly = yf - y0f, lx = xf - x0f;
        int y0 = (int)y0f, x0 = (int)x0f;
        int y1 = y0 + 1,  x1 = x0 + 1;

        float a = (1.f - ly) * (1.f - lx);
        float b = (1.f - ly) * lx;
        float c = ly * (1.f - lx);
        float d = ly * lx;

        bool vy0 = (y0 >= 0) & (y0 < H_IN);
        bool vy1 = (y1 >= 0) & (y1 < H_IN);
        bool vx0 = (x0 >= 0) & (x0 < W_IN);
        bool vx1 = (x1 >= 0) & (x1 < W_IN);
        w00[s] = a * (float)(vy0 & vx0);
        w01[s] = b * (float)(vy0 & vx1);
        w10[s] = c * (float)(vy1 & vx0);
        w11[s] = d * (float)(vy1 & vx1);

        int cy0 = min(max(y0, 0), H_IN - 1);
        int cy1 = min(max(y1, 0), H_IN - 1);
        int cx0 = min(max(x0, 0), W_IN - 1);
        int cx1 = min(max(x1, 0), W_IN - 1);
        i00[s] = cy0 * W_IN + cx0;
        i01[s] = cy0 * W_IN + cx1;
        i10[s] = cy1 * W_IN + cx0;
        i11[s] = cy1 * W_IN + cx1;
    }

    const __half* xb = g_Xf + ((size_t)n * C_IN + g * CG) * (H_IN * W_IN);
    size_t base = ((size_t)n * KDIM + (size_t)(g * KKN + k) * CG) * NP + p;
    __half* sp = g_S + base;

    #pragma unroll 4
    for (int c = 0; c < CG; ++c) {
        const __half* xc = xb + (size_t)c * (H_IN * W_IN);
        float v0 = w00[0] * __half2float(__ldg(xc + i00[0]))
                 + w01[0] * __half2float(__ldg(xc + i01[0]))
                 + w10[0] * __half2float(__ldg(xc + i10[0]))
                 + w11[0] * __half2float(__ldg(xc + i11[0]));
        float v1 = w00[1] * __half2float(__ldg(xc + i00[1]))
                 + w01[1] * __half2float(__ldg(xc + i01[1]))
                 + w10[1] * __half2float(__ldg(xc + i10[1]))
                 + w11[1] * __half2float(__ldg(xc + i11[1]));
        __half2 hp = __floats2half2_rn(v0, v1);
        *reinterpret_cast<uint32_t*>(sp + (size_t)c * NP) = *reinterpret_cast<uint32_t*>(&hp);
    }
}

// ================= GEMM2: HMMA fp16 single-pass =================
#define A_PITCH 80
#define B_PITCH 272
#define SA_PLANE (128 * A_PITCH)                 // 10240
#define SB_PLANE (32 * B_PITCH)                  // 8704
#define OFF_A 0
#define OFF_B SA_PLANE
#define BUF_BYTES (SA_PLANE + SB_PLANE)          // 18944
#define SMEM2_BYTES (2 * BUF_BYTES)              // 37888

__global__ void __launch_bounds__(256, 2)
gemm2_mma(float* __restrict__ out)
{
    extern __shared__ char smem[];
    const uint32_t sb = smem_u32(smem);

    const int tid = threadIdx.x;
    const int wid = tid >> 5;
    const int l   = tid & 31;

    const int my = blockIdx.x;
    const int bx = blockIdx.y;
    const int n  = blockIdx.z;

    const int wm = (wid & 1) * 64;
    const int wn = (wid >> 1) * 32;

    const __half* Ap = g_A + (size_t)my * 128 * KDIM;
    const __half* Sp = g_S + (size_t)n * KDIM * NP + (size_t)bx * 128;

    const int a_row = ((l >> 3) & 1) * 8 + (l & 7);
    const int a_kb  = (l >> 4) * 8;
    const int b_kr  = ((l >> 3) & 1) * 8 + (l & 7);
    const int b_nb  = (l >> 4) * 8;

    float acc[4][4][4];
    #pragma unroll
    for (int i = 0; i < 4; ++i)
        #pragma unroll
        for (int j = 0; j < 4; ++j)
            #pragma unroll
            for (int q = 0; q < 4; ++q) acc[i][j][q] = 0.f;

    auto load_tile = [&](int kt, int b) {
        uint32_t base = sb + b * BUF_BYTES;
        #pragma unroll
        for (int i = 0; i < 2; ++i) {
            int c = tid + i * 256;
            int r = c >> 2, j = c & 3;
            cp16(base + OFF_A + r * A_PITCH + j * 16, Ap + (size_t)r * KDIM + kt + j * 8);
        }
        #pragma unroll
        for (int i = 0; i < 2; ++i) {
            int c = tid + i * 256;
            int r = c >> 4, j = c & 15;
            cp16(base + OFF_B + r * B_PITCH + j * 16, Sp + (size_t)(kt + r) * NP + j * 8);
        }
        CP_COMMIT();
    };

    load_tile(0, 0);

    for (int t = 0; t < NT; ++t) {
        int b = t & 1;
        if (t + 1 < NT) {
            load_tile((t + 1) * BK, b ^ 1);
            CP_WAIT(1);
        } else {
            CP_WAIT(0);
        }
        __syncthreads();

        uint32_t base = sb + b * BUF_BYTES;
        #pragma unroll
        for (int k16 = 0; k16 < BK; k16 += 16) {
            uint32_t af[4][4], bf[4][2];
            #pragma unroll
            for (int mt = 0; mt < 4; ++mt)
                ldsm_x4(af[mt], base + OFF_A + (wm + mt * 16 + a_row) * A_PITCH
                                + (k16 + a_kb) * 2);
            #pragma unroll
            for (int nt2 = 0; nt2 < 2; ++nt2) {
                uint32_t r[4];
                ldsm_x4t(r, base + OFF_B + (k16 + b_kr) * B_PITCH
                            + (wn + nt2 * 16 + b_nb) * 2);
                bf[nt2*2][0] = r[0]; bf[nt2*2][1] = r[1];
                bf[nt2*2+1][0] = r[2]; bf[nt2*2+1][1] = r[3];
            }
            #pragma unroll
            for (int mt = 0; mt < 4; ++mt)
                #pragma unroll
                for (int nt = 0; nt < 4; ++nt)
                    mma_f16(acc[mt][nt], af[mt], bf[nt]);
        }
        __syncthreads();
    }

    float* ob = out + ((size_t)n * M_OUT + my * 128 + wm) * NP + (size_t)bx * 128 + wn;
    #pragma unroll
    for (int mt = 0; mt < 4; ++mt) {
        #pragma unroll
        for (int nt = 0; nt < 4; ++nt) {
            int row = mt * 16 + (l >> 2);
            int col = nt * 8 + (l & 3) * 2;
            float* p0 = ob + (size_t)row * NP + col;
            *reinterpret_cast<float2*>(p0) =
                make_float2(acc[mt][nt][0], acc[mt][nt][1]);
            *reinterpret_cast<float2*>(p0 + 8 * NP) =
                make_float2(acc[mt][nt][2], acc[mt][nt][3]);
        }
    }
}

// ---------------- launch ----------------
extern "C" void kernel_launch(void* const* d_in, const int* in_sizes, int n_in,
                              void* d_out, int out_size) {
    const float* x    = (const float*)d_in[0];
    const float* offw = (const float*)d_in[1];
    const float* offb = (const float*)d_in[2];
    const float* dw   = (const float*)d_in[3];
    float* out = (float*)d_out;

    cudaFuncSetAttribute(gemm1_mma, cudaFuncAttributeMaxDynamicSharedMemorySize, SMEM1);
    cudaFuncSetAttribute(gemm2_mma, cudaFuncAttributeMaxDynamicSharedMemorySize, SMEM2_BYTES);

    prep_w  <<<(M_OUT * KDIM + 255) / 256, 256>>>(dw);
    prep_w1 <<<(M_PAD * KDIM + 255) / 256, 256>>>(offw);
    prep_xall<<<(int)((XFULL + 255) / 256), 256>>>(x);
    // 1) offsets via tensor cores (fp16 single-pass)
    {
        dim3 grid(NP / 128, 1, N_B);
        gemm1_mma<<<grid, 256, SMEM1>>>(offb);
    }
    // 2) bilinear sampled matrix from fp16 x -> single fp16 plane
    {
        dim3 grid(NP / 512, GRP * KKN, N_B);
        gather_sampled<<<grid, 256>>>();
    }
    // 3) out = dw @ sampled (fp16 single-pass)
    {
        dim3 grid(2, NP / 128, N_B);
        gemm2_mma<<<grid, 256, SMEM2_BYTES>>>(out);
    }
}

// round 17
// speedup vs baseline: 1.1728x; 1.0577x over previous
#include <cuda_runtime.h>
#include <cuda_fp16.h>
#include <cstdint>

// ---------------- problem constants ----------------
#define H_IN   132
#define W_IN   132
#define C_IN   256
#define N_B    2
#define NP     16384
#define KKN    9
#define GRP    4
#define CG     64
#define KDIM   2304
#define M_OFF  72
#define M_PAD  80
#define M_OUT  256
#define BK     64
#define NT     (KDIM / BK)       // 36 k-tiles

typedef unsigned long long ULL;

// ---------------- scratch (device globals) ----------------
__device__ __half g_S[(size_t)N_B * KDIM * NP];         // sampled matrix, fp16, K-major
__device__ __half g_A[(size_t)M_OUT * KDIM];            // deform weights fp16
__device__ __half g_A1[(size_t)M_PAD * KDIM];           // offset weights fp16
#define XPLANE ((size_t)N_B * C_IN * H_IN * 128)
__device__ __half g_X[3 * XPLANE];                      // x fp16, 3 kx-shifted copies (gemm1)
#define XFULL ((size_t)N_B * C_IN * H_IN * W_IN)
__device__ __half g_Xf[XFULL];                          // full fp16 copy of x (gather)
__device__ float g_off[(size_t)N_B * M_OFF * NP];

// ---------------- helpers ----------------
__device__ __forceinline__ uint32_t smem_u32(const void* p) {
    uint32_t a;
    asm("{ .reg .u64 t; cvta.to.shared.u64 t, %1; cvt.u32.u64 %0, t; }" : "=r"(a) : "l"(p));
    return a;
}
__device__ __forceinline__ void cp16(uint32_t dst, const void* src) {
    ULL g;
    asm("cvta.to.global.u64 %0, %1;" : "=l"(g) : "l"(src));
    asm volatile("cp.async.cg.shared.global [%0], [%1], 16;" :: "r"(dst), "l"(g) : "memory");
}
#define CP_COMMIT() asm volatile("cp.async.commit_group;" ::: "memory")
#define CP_WAIT(n)  asm volatile("cp.async.wait_group %0;" :: "n"(n) : "memory")

__device__ __forceinline__ void ldsm_x4(uint32_t* r, uint32_t addr) {
    asm volatile("ldmatrix.sync.aligned.m8n8.x4.shared.b16 {%0,%1,%2,%3}, [%4];"
                 : "=r"(r[0]), "=r"(r[1]), "=r"(r[2]), "=r"(r[3]) : "r"(addr));
}
__device__ __forceinline__ void ldsm_x4t(uint32_t* r, uint32_t addr) {
    asm volatile("ldmatrix.sync.aligned.m8n8.x4.trans.shared.b16 {%0,%1,%2,%3}, [%4];"
                 : "=r"(r[0]), "=r"(r[1]), "=r"(r[2]), "=r"(r[3]) : "r"(addr));
}
__device__ __forceinline__ void mma_f16(float* c, const uint32_t* a, const uint32_t* b) {
    asm volatile(
        "mma.sync.aligned.m16n8k16.row.col.f32.f16.f16.f32 "
        "{%0,%1,%2,%3}, {%4,%5,%6,%7}, {%8,%9}, {%0,%1,%2,%3};"
        : "+f"(c[0]), "+f"(c[1]), "+f"(c[2]), "+f"(c[3])
        : "r"(a[0]), "r"(a[1]), "r"(a[2]), "r"(a[3]), "r"(b[0]), "r"(b[1]));
}

// ================= prep kernels =================
__global__ void prep_w(const float* __restrict__ dw) {
    int idx = blockIdx.x * 256 + threadIdx.x;
    if (idx >= M_OUT * KDIM) return;
    int m = idx / KDIM, j = idx - m * KDIM;
    int g = j / (KKN * CG);
    int r = j - g * (KKN * CG);
    int k = r / CG;
    int c = r - k * CG;
    g_A[idx] = __float2half_rn(dw[((size_t)m * C_IN + g * CG + c) * KKN + k]);
}
__global__ void prep_w1(const float* __restrict__ offw) {
    int idx = blockIdx.x * 256 + threadIdx.x;
    if (idx >= M_PAD * KDIM) return;
    int m = idx / KDIM, j = idx - m * KDIM;
    float v = (m < M_OFF) ? offw[(size_t)m * KDIM + j] : 0.f;
    g_A1[idx] = __float2half_rn(v);
}
// fused: read x once, write full fp16 copy + 3 kx-shifted 128-wide planes
__global__ void prep_xall(const float* __restrict__ x) {
    size_t idx = (size_t)blockIdx.x * 256 + threadIdx.x;
    if (idx >= XFULL) return;
    __half h = __float2half_rn(x[idx]);
    g_Xf[idx] = h;
    int wo = (int)(idx % W_IN);
    size_t rest = idx / W_IN;            // (n*C + ci)*H + y
    #pragma unroll
    for (int kx = 0; kx < 3; ++kx) {
        int w0 = wo - 2 * kx;
        if (w0 >= 0 && w0 < 128)
            g_X[kx * XPLANE + rest * 128 + w0] = h;
    }
}

// ================= GEMM1: offsets via HMMA fp16 single-pass (80m x 128n x 64k) =================
#define A1_PITCH 144
#define B1_PITCH 272
#define SA1 (M_PAD * A1_PITCH)           // 11520
#define SB1 (BK * B1_PITCH)              // 17408
#define OFF_A1 0
#define OFF_B1 SA1
#define BUF1 (SA1 + SB1)                 // 28928
#define SMEM1 (2 * BUF1)                 // 57856

__global__ void __launch_bounds__(256, 2)
gemm1_mma(const float* __restrict__ bias)
{
    extern __shared__ char smem[];
    const uint32_t sb = smem_u32(smem);

    const int tid = threadIdx.x;
    const int l   = tid & 31;
    const int wid = tid >> 5;
    const int n   = blockIdx.z;
    const int p0  = blockIdx.x * 128;
    const int ho0 = blockIdx.x;
    const int wn  = wid * 16;

    const int a_row = ((l >> 3) & 1) * 8 + (l & 7);
    const int a_kb  = (l >> 4) * 8;
    const int b_kr  = ((l >> 3) & 1) * 8 + (l & 7);
    const int b_nb  = (l >> 4) * 8;

    float acc[5][2][4];
    #pragma unroll
    for (int i = 0; i < 5; ++i)
        #pragma unroll
        for (int j = 0; j < 2; ++j)
            #pragma unroll
            for (int q = 0; q < 4; ++q) acc[i][j][q] = 0.f;

    auto load_tile = [&](int kt, int b) {
        uint32_t base = sb + b * BUF1;
        // A: 80 rows x 8 chunks = 640 chunks
        #pragma unroll
        for (int i = 0; i < 3; ++i) {
            int c = tid + i * 256;
            if (c < 640) {
                int r = c >> 3, j = c & 7;
                cp16(base + OFF_A1 + r * A1_PITCH + j * 16,
                     g_A1 + (size_t)r * KDIM + kt + j * 8);
            }
        }
        // B: 64 k-rows x 16 chunks = 1024 chunks
        #pragma unroll
        for (int i = 0; i < 4; ++i) {
            int c  = tid + i * 256;
            int r  = c >> 4;
            int ch = c & 15;
            int j  = kt + r;
            int ci = j / 9;
            int kk = j - ci * 9;
            int ky = kk / 3;
            int kx = kk - ky * 3;
            int y  = ho0 + 2 * ky;
            size_t src = (size_t)kx * XPLANE
                       + (((size_t)n * C_IN + ci) * H_IN + y) * 128 + ch * 8;
            cp16(base + OFF_B1 + r * B1_PITCH + ch * 16, g_X + src);
        }
        CP_COMMIT();
    };

    load_tile(0, 0);

    for (int t = 0; t < NT; ++t) {
        int b = t & 1;
        if (t + 1 < NT) {
            load_tile((t + 1) * BK, b ^ 1);
            CP_WAIT(1);
        } else {
            CP_WAIT(0);
        }
        __syncthreads();

        uint32_t base = sb + b * BUF1;
        #pragma unroll
        for (int k16 = 0; k16 < BK; k16 += 16) {
            uint32_t ah[5][4], bf[2][2];
            #pragma unroll
            for (int mt = 0; mt < 5; ++mt)
                ldsm_x4(ah[mt], base + OFF_A1 + (mt * 16 + a_row) * A1_PITCH
                                + (k16 + a_kb) * 2);
            {
                uint32_t r[4];
                ldsm_x4t(r, base + OFF_B1 + (k16 + b_kr) * B1_PITCH
                            + (wn + b_nb) * 2);
                bf[0][0] = r[0]; bf[0][1] = r[1];
                bf[1][0] = r[2]; bf[1][1] = r[3];
            }
            #pragma unroll
            for (int mt = 0; mt < 5; ++mt)
                #pragma unroll
                for (int nt = 0; nt < 2; ++nt)
                    mma_f16(acc[mt][nt], ah[mt], bf[nt]);
        }
        __syncthreads();
    }

    float* ob = g_off + (size_t)n * M_OFF * NP + p0 + wn;
    #pragma unroll
    for (int mt = 0; mt < 5; ++mt) {
        int row = mt * 16 + (l >> 2);
        float bv0 = bias[row];
        #pragma unroll
        for (int nt = 0; nt < 2; ++nt) {
            int col = nt * 8 + (l & 3) * 2;
            float* p = ob + (size_t)row * NP + col;
            *reinterpret_cast<float2*>(p) =
                make_float2(acc[mt][nt][0] + bv0, acc[mt][nt][1] + bv0);
        }
        if (mt < 4) {
            float bv1 = bias[row + 8];
            #pragma unroll
            for (int nt = 0; nt < 2; ++nt) {
                int col = nt * 8 + (l & 3) * 2;
                float* p = ob + (size_t)(row + 8) * NP + col;
                *reinterpret_cast<float2*>(p) =
                    make_float2(acc[mt][nt][2] + bv1, acc[mt][nt][3] + bv1);
            }
        }
    }
}

// ================= gather: bilinear from fp16 x, 2 px/thread =================
__global__ void gather_sampled() {
    int n  = blockIdx.z;
    int gk = blockIdx.y;
    int g  = gk / KKN, k = gk % KKN;
    int p  = (blockIdx.x * blockDim.x + threadIdx.x) * 2;
    int ho = p >> 7;
    int ky = k / 3, kx = k % 3;

    const float* offbase = g_off + ((size_t)n * M_OFF + g * 18 + k * 2) * NP + p;
    float2 dy = *reinterpret_cast<const float2*>(offbase);
    float2 dx = *reinterpret_cast<const float2*>(offbase + NP);

    float w00[2], w01[2], w10[2], w11[2];
    int i00[2], i01[2], i10[2], i11[2];
    #pragma unroll
    for (int s = 0; s < 2; ++s) {
        int wo = (p + s) & 127;
        float yf = (s ? dy.y : dy.x) + (float)(ky * 2 + ho);
        float xf = (s ? dx.y : dx.x) + (float)(kx * 2 + wo);
        float y0f = floorf(yf), x0f = floorf(xf);
        float ly = yf - y0f, lx = xf - x0f;
        int y0 = (int)y0f, x0 = (int)x0f;
        int y1 = y0 + 1,  x1 = x0 + 1;

        float a = (1.f - ly) * (1.f - lx);
        float b = (1.f - ly) * lx;
        float c = ly * (1.f - lx);
        float d = ly * lx;

        bool vy0 = (y0 >= 0) & (y0 < H_IN);
        bool vy1 = (y1 >= 0) & (y1 < H_IN);
        bool vx0 = (x0 >= 0) & (x0 < W_IN);
        bool vx1 = (x1 >= 0) & (x1 < W_IN);
        w00[s] = a * (float)(vy0 & vx0);
        w01[s] = b * (float)(vy0 & vx1);
        w10[s] = c * (float)(vy1 & vx0);
        w11[s] = d * (float)(vy1 & vx1);

        int cy0 = min(max(y0, 0), H_IN - 1);
        int cy1 = min(max(y1, 0), H_IN - 1);
        int cx0 = min(max(x0, 0), W_IN - 1);
        int cx1 = min(max(x1, 0), W_IN - 1);
        i00[s] = cy0 * W_IN + cx0;
        i01[s] = cy0 * W_IN + cx1;
        i10[s] = cy1 * W_IN + cx0;
        i11[s] = cy1 * W_IN + cx1;
    }

    const __half* xb = g_Xf + ((size_t)n * C_IN + g * CG) * (H_IN * W_IN);
    size_t base = ((size_t)n * KDIM + (size_t)(g * KKN + k) * CG) * NP + p;
    __half* sp = g_S + base;

    #pragma unroll 4
    for (int c = 0; c < CG; ++c) {
        const __half* xc = xb + (size_t)c * (H_IN * W_IN);
        float v0 = w00[0] * __half2float(__ldg(xc + i00[0]))
                 + w01[0] * __half2float(__ldg(xc + i01[0]))
                 + w10[0] * __half2float(__ldg(xc + i10[0]))
                 + w11[0] * __half2float(__ldg(xc + i11[0]));
        float v1 = w00[1] * __half2float(__ldg(xc + i00[1]))
                 + w01[1] * __half2float(__ldg(xc + i01[1]))
                 + w10[1] * __half2float(__ldg(xc + i10[1]))
                 + w11[1] * __half2float(__ldg(xc + i11[1]));
        __half2 hp = __floats2half2_rn(v0, v1);
        *reinterpret_cast<uint32_t*>(sp + (size_t)c * NP) = *reinterpret_cast<uint32_t*>(&hp);
    }
}

// ================= GEMM2: HMMA fp16 single-pass (128m x 128n x 64k) =================
#define A_PITCH 144
#define B_PITCH 272
#define SA_PLANE (128 * A_PITCH)                 // 18432
#define SB_PLANE (BK * B_PITCH)                  // 17408
#define OFF_A 0
#define OFF_B SA_PLANE
#define BUF_BYTES (SA_PLANE + SB_PLANE)          // 35840
#define SMEM2_BYTES (2 * BUF_BYTES)              // 71680

__global__ void __launch_bounds__(256, 2)
gemm2_mma(float* __restrict__ out)
{
    extern __shared__ char smem[];
    const uint32_t sb = smem_u32(smem);

    const int tid = threadIdx.x;
    const int wid = tid >> 5;
    const int l   = tid & 31;

    const int my = blockIdx.x;
    const int bx = blockIdx.y;
    const int n  = blockIdx.z;

    const int wm = (wid & 1) * 64;
    const int wn = (wid >> 1) * 32;

    const __half* Ap = g_A + (size_t)my * 128 * KDIM;
    const __half* Sp = g_S + (size_t)n * KDIM * NP + (size_t)bx * 128;

    const int a_row = ((l >> 3) & 1) * 8 + (l & 7);
    const int a_kb  = (l >> 4) * 8;
    const int b_kr  = ((l >> 3) & 1) * 8 + (l & 7);
    const int b_nb  = (l >> 4) * 8;

    float acc[4][4][4];
    #pragma unroll
    for (int i = 0; i < 4; ++i)
        #pragma unroll
        for (int j = 0; j < 4; ++j)
            #pragma unroll
            for (int q = 0; q < 4; ++q) acc[i][j][q] = 0.f;

    auto load_tile = [&](int kt, int b) {
        uint32_t base = sb + b * BUF_BYTES;
        // A: 128 rows x 8 chunks = 1024
        #pragma unroll
        for (int i = 0; i < 4; ++i) {
            int c = tid + i * 256;
            int r = c >> 3, j = c & 7;
            cp16(base + OFF_A + r * A_PITCH + j * 16, Ap + (size_t)r * KDIM + kt + j * 8);
        }
        // B: 64 rows x 16 chunks = 1024
        #pragma unroll
        for (int i = 0; i < 4; ++i) {
            int c = tid + i * 256;
            int r = c >> 4, j = c & 15;
            cp16(base + OFF_B + r * B_PITCH + j * 16, Sp + (size_t)(kt + r) * NP + j * 8);
        }
        CP_COMMIT();
    };

    load_tile(0, 0);

    for (int t = 0; t < NT; ++t) {
        int b = t & 1;
        if (t + 1 < NT) {
            load_tile((t + 1) * BK, b ^ 1);
            CP_WAIT(1);
        } else {
            CP_WAIT(0);
        }
        __syncthreads();

        uint32_t base = sb + b * BUF_BYTES;
        #pragma unroll
        for (int k16 = 0; k16 < BK; k16 += 16) {
            uint32_t af[4][4], bf[4][2];
            #pragma unroll
            for (int mt = 0; mt < 4; ++mt)
                ldsm_x4(af[mt], base + OFF_A + (wm + mt * 16 + a_row) * A_PITCH
                                + (k16 + a_kb) * 2);
            #pragma unroll
            for (int nt2 = 0; nt2 < 2; ++nt2) {
                uint32_t r[4];
                ldsm_x4t(r, base + OFF_B + (k16 + b_kr) * B_PITCH
                            + (wn + nt2 * 16 + b_nb) * 2);
                bf[nt2*2][0] = r[0]; bf[nt2*2][1] = r[1];
                bf[nt2*2+1][0] = r[2]; bf[nt2*2+1][1] = r[3];
            }
            #pragma unroll
            for (int mt = 0; mt < 4; ++mt)
                #pragma unroll
                for (int nt = 0; nt < 4; ++nt)
                    mma_f16(acc[mt][nt], af[mt], bf[nt]);
        }
        __syncthreads();
    }

    float* ob = out + ((size_t)n * M_OUT + my * 128 + wm) * NP + (size_t)bx * 128 + wn;
    #pragma unroll
    for (int mt = 0; mt < 4; ++mt) {
        #pragma unroll
        for (int nt = 0; nt < 4; ++nt) {
            int row = mt * 16 + (l >> 2);
            int col = nt * 8 + (l & 3) * 2;
            float* p0 = ob + (size_t)row * NP + col;
            *reinterpret_cast<float2*>(p0) =
                make_float2(acc[mt][nt][0], acc[mt][nt][1]);
            *reinterpret_cast<float2*>(p0 + 8 * NP) =
                make_float2(acc[mt][nt][2], acc[mt][nt][3]);
        }
    }
}

// ---------------- launch ----------------
extern "C" void kernel_launch(void* const* d_in, const int* in_sizes, int n_in,
                              void* d_out, int out_size) {
    const float* x    = (const float*)d_in[0];
    const float* offw = (const float*)d_in[1];
    const float* offb = (const float*)d_in[2];
    const float* dw   = (const float*)d_in[3];
    float* out = (float*)d_out;

    cudaFuncSetAttribute(gemm1_mma, cudaFuncAttributeMaxDynamicSharedMemorySize, SMEM1);
    cudaFuncSetAttribute(gemm2_mma, cudaFuncAttributeMaxDynamicSharedMemorySize, SMEM2_BYTES);

    prep_w  <<<(M_OUT * KDIM + 255) / 256, 256>>>(dw);
    prep_w1 <<<(M_PAD * KDIM + 255) / 256, 256>>>(offw);
    prep_xall<<<(int)((XFULL + 255) / 256), 256>>>(x);
    // 1) offsets via tensor cores (fp16 single-pass, BK=64)
    {
        dim3 grid(NP / 128, 1, N_B);
        gemm1_mma<<<grid, 256, SMEM1>>>(offb);
    }
    // 2) bilinear sampled matrix from fp16 x -> single fp16 plane
    {
        dim3 grid(NP / 512, GRP * KKN, N_B);
        gather_sampled<<<grid, 256>>>();
    }
    // 3) out = dw @ sampled (fp16 single-pass, BK=64)
    {
        dim3 grid(2, NP / 128, N_B);
        gemm2_mma<<<grid, 256, SMEM2_BYTES>>>(out);
    }
}